// round 1
// baseline (speedup 1.0000x reference)
#include <cuda_runtime.h>
#include <math.h>

#define B_   4096
#define T_   32
#define H_   512
#define NG   2048   // 4*H
#define EMB_ 64
#define V_   256
#define O_   64

// ---------- persistent scratch (no allocations allowed) ----------
__device__ float d_table[2][V_][NG];      // per-char gate preactivation (+both biases), gate-interleaved
__device__ float d_wt[2][H_][NG];         // Whh transposed to [k][n], gate-interleaved columns
__device__ float d_h[2][2][B_ * H_];      // [dir][pingpong][b*H+h]
__device__ float d_c[2][B_ * H_];         // cell state (updated in place)

__device__ __forceinline__ int jmap(int n) { return ((n & 3) << 9) + (n >> 2); }

__device__ __forceinline__ float sig_f(float x)  { return 1.0f / (1.0f + __expf(-x)); }

// ---------- one-off precompute ----------
__global__ void build_table(const float* __restrict__ emb,
                            const float* __restrict__ Wih1, const float* __restrict__ bih1, const float* __restrict__ bhh1,
                            const float* __restrict__ Wih2, const float* __restrict__ bih2, const float* __restrict__ bhh2) {
    int n   = blockIdx.x * 128 + threadIdx.x;   // 0..2047
    int v   = blockIdx.y;                        // 0..255
    int dir = blockIdx.z;
    const float* Wih = dir ? Wih2 : Wih1;
    const float* bi  = dir ? bih2 : bih1;
    const float* bh  = dir ? bhh2 : bhh1;
    int j = jmap(n);
    float s = bi[j] + bh[j];
    const float* e = emb + v * EMB_;
    const float* w = Wih + j * EMB_;
#pragma unroll 16
    for (int k = 0; k < EMB_; k++) s += e[k] * w[k];
    d_table[dir][v][n] = s;
}

__global__ void build_wt(const float* __restrict__ Whh1, const float* __restrict__ Whh2) {
    int n   = blockIdx.x * 256 + threadIdx.x;   // 0..2047
    int k   = blockIdx.y;                        // 0..511
    int dir = blockIdx.z;
    const float* W = dir ? Whh2 : Whh1;
    d_wt[dir][k][n] = W[jmap(n) * H_ + k];
}

__global__ void init_state() {
    int i = blockIdx.x * 256 + threadIdx.x;
    if (i < B_ * H_) {
        d_h[0][0][i] = 0.f; d_h[1][0][i] = 0.f;
        d_c[0][i]    = 0.f; d_c[1][i]    = 0.f;
    }
}

// ---------- fused recurrent step: C = h_prev @ Whh^T (+table+bias) -> gates -> h,c ----------
// Tile: 128(B) x 128(N) x 16(K), 256 threads, 8x8 microtile (4+4 split).
__global__ void __launch_bounds__(256, 2) lstm_step(const int* __restrict__ x, int t, int pp) {
    const int dir  = blockIdx.z;
    const int tcol = dir ? (T_ - 1 - t) : t;
    const float* __restrict__ hprev = d_h[dir][pp];
    float*       __restrict__ hnext = d_h[dir][pp ^ 1];
    float*       __restrict__ cst   = d_c[dir];
    const float* __restrict__ W     = &d_wt[dir][0][0];    // [512][2048]

    const int b0  = blockIdx.y * 128;
    const int n0  = blockIdx.x * 128;
    const int tid = threadIdx.x;
    const int tx  = tid & 15;
    const int ty  = tid >> 4;

    __shared__ __align__(16) float As[2][16][132];  // [k][m], padded (132%4==0 keeps float4 alignment)
    __shared__ __align__(16) float Bs[2][16][128];  // [k][n]

    // A loader: thread -> (row am, k-quad ak); covers rows am and am+64
    const int am = tid >> 2;          // 0..63
    const int ak = (tid & 3) * 4;     // 0,4,8,12
    // B loader: thread -> (k row bk / bk+8, 4 cols at bn)
    const int bk = tid >> 5;          // 0..7
    const int bn = (tid & 31) * 4;    // 0..124

    float acc[8][8];
#pragma unroll
    for (int i = 0; i < 8; i++)
#pragma unroll
        for (int j = 0; j < 8; j++) acc[i][j] = 0.f;

    // prologue: stage k-tile 0
    float4 a0 = *(const float4*)&hprev[(b0 + am) * H_ + ak];
    float4 a1 = *(const float4*)&hprev[(b0 + am + 64) * H_ + ak];
    float4 v0 = *(const float4*)&W[(bk) * NG + n0 + bn];
    float4 v1 = *(const float4*)&W[(bk + 8) * NG + n0 + bn];
    As[0][ak + 0][am] = a0.x; As[0][ak + 1][am] = a0.y; As[0][ak + 2][am] = a0.z; As[0][ak + 3][am] = a0.w;
    As[0][ak + 0][am + 64] = a1.x; As[0][ak + 1][am + 64] = a1.y; As[0][ak + 2][am + 64] = a1.z; As[0][ak + 3][am + 64] = a1.w;
    *(float4*)&Bs[0][bk][bn]     = v0;
    *(float4*)&Bs[0][bk + 8][bn] = v1;
    __syncthreads();

    for (int kt = 0; kt < 32; kt++) {
        const int cur = kt & 1;
        if (kt < 31) {
            const int k0n = (kt + 1) * 16;
            a0 = *(const float4*)&hprev[(b0 + am) * H_ + k0n + ak];
            a1 = *(const float4*)&hprev[(b0 + am + 64) * H_ + k0n + ak];
            v0 = *(const float4*)&W[(k0n + bk) * NG + n0 + bn];
            v1 = *(const float4*)&W[(k0n + bk + 8) * NG + n0 + bn];
        }
#pragma unroll
        for (int kk = 0; kk < 16; kk++) {
            float a[8], b[8];
            *(float4*)&a[0] = *(const float4*)&As[cur][kk][ty * 4];
            *(float4*)&a[4] = *(const float4*)&As[cur][kk][64 + ty * 4];
            *(float4*)&b[0] = *(const float4*)&Bs[cur][kk][tx * 4];
            *(float4*)&b[4] = *(const float4*)&Bs[cur][kk][64 + tx * 4];
#pragma unroll
            for (int i = 0; i < 8; i++)
#pragma unroll
                for (int j = 0; j < 8; j++)
                    acc[i][j] += a[i] * b[j];
        }
        if (kt < 31) {
            const int nxt = cur ^ 1;
            As[nxt][ak + 0][am] = a0.x; As[nxt][ak + 1][am] = a0.y; As[nxt][ak + 2][am] = a0.z; As[nxt][ak + 3][am] = a0.w;
            As[nxt][ak + 0][am + 64] = a1.x; As[nxt][ak + 1][am + 64] = a1.y; As[nxt][ak + 2][am + 64] = a1.z; As[nxt][ak + 3][am + 64] = a1.w;
            *(float4*)&Bs[nxt][bk][bn]     = v0;
            *(float4*)&Bs[nxt][bk + 8][bn] = v1;
            __syncthreads();
        }
    }

    // epilogue: gates + cell update. Each 4-col quad = one hidden unit (i,f,g,o).
#pragma unroll
    for (int ri = 0; ri < 8; ri++) {
        const int b  = b0 + ((ri < 4) ? (ty * 4 + ri) : (64 + ty * 4 + ri - 4));
        const int ch = x[b * T_ + tcol];
        const float* trow = d_table[dir][ch];
#pragma unroll
        for (int q = 0; q < 2; q++) {
            const int cb = (q == 0) ? (tx * 4) : (64 + tx * 4);
            const float4 tb = *(const float4*)&trow[n0 + cb];
            float gi = acc[ri][q * 4 + 0] + tb.x;
            float gf = acc[ri][q * 4 + 1] + tb.y;
            float gg = acc[ri][q * 4 + 2] + tb.z;
            float go = acc[ri][q * 4 + 3] + tb.w;
            gi = sig_f(gi);
            gf = sig_f(gf);
            go = sig_f(go);
            const int hi = (n0 + cb) >> 2;
            const int ci = b * H_ + hi;
            float cv = cst[ci];
            cv = gf * cv + gi * tanhf(gg);
            cst[ci]   = cv;
            hnext[ci] = go * tanhf(cv);
        }
    }
}

// ---------- classifier head + softmax ----------
__global__ void head_kernel(const float* __restrict__ Wlin, const float* __restrict__ blin,
                            float* __restrict__ out) {
    const int b   = blockIdx.x;
    const int tid = threadIdx.x;         // 256 threads = 8 warps
    const int w   = tid >> 5;
    const int lane = tid & 31;

    __shared__ __align__(16) float hrow[1024];
    __shared__ float lg[O_];
    __shared__ float red[2];

    for (int i = tid; i < H_; i += 256) {
        hrow[i]        = d_h[0][0][b * H_ + i];
        hrow[H_ + i]   = d_h[1][0][b * H_ + i];
    }
    __syncthreads();

    // each warp computes 8 outputs
    const float4* hr4 = (const float4*)hrow;
#pragma unroll
    for (int oo = 0; oo < 8; oo++) {
        const int o = w * 8 + oo;
        const float4* wl = (const float4*)(Wlin + o * 1024);
        float s = 0.f;
#pragma unroll
        for (int it = 0; it < 8; it++) {
            float4 a  = hr4[it * 32 + lane];
            float4 bw = wl[it * 32 + lane];
            s += a.x * bw.x + a.y * bw.y + a.z * bw.z + a.w * bw.w;
        }
#pragma unroll
        for (int off = 16; off; off >>= 1) s += __shfl_down_sync(0xffffffffu, s, off);
        if (lane == 0) lg[o] = s + blin[o];
    }
    __syncthreads();

    if (tid == 0) {
        float m = lg[0];
        for (int i = 1; i < O_; i++) m = fmaxf(m, lg[i]);
        red[0] = m;
    }
    __syncthreads();
    if (tid < O_) lg[tid] = expf(lg[tid] - red[0]);
    __syncthreads();
    if (tid == 0) {
        float s = 0.f;
        for (int i = 0; i < O_; i++) s += lg[i];
        red[1] = 1.0f / s;
    }
    __syncthreads();
    if (tid < O_) out[b * O_ + tid] = lg[tid] * red[1];
}

// ---------- launch ----------
extern "C" void kernel_launch(void* const* d_in, const int* in_sizes, int n_in,
                              void* d_out, int out_size) {
    const int*   x    = (const int*)d_in[0];
    // d_in[1] = mask (unused by reference)
    const float* emb  = (const float*)d_in[2];
    const float* Wih1 = (const float*)d_in[3];
    const float* Whh1 = (const float*)d_in[4];
    const float* bih1 = (const float*)d_in[5];
    const float* bhh1 = (const float*)d_in[6];
    const float* Wih2 = (const float*)d_in[7];
    const float* Whh2 = (const float*)d_in[8];
    const float* bih2 = (const float*)d_in[9];
    const float* bhh2 = (const float*)d_in[10];
    const float* Wlin = (const float*)d_in[11];
    const float* blin = (const float*)d_in[12];
    float* out = (float*)d_out;

    dim3 g1(NG / 128, V_, 2);
    build_table<<<g1, 128>>>(emb, Wih1, bih1, bhh1, Wih2, bih2, bhh2);
    dim3 g2(NG / 256, H_, 2);
    build_wt<<<g2, 256>>>(Whh1, Whh2);
    init_state<<<(B_ * H_ + 255) / 256, 256>>>();

    dim3 gs(NG / 128, B_ / 128, 2);   // (16, 32, 2)
    for (int t = 0; t < T_; t++) {
        lstm_step<<<gs, 256>>>(x, t, t & 1);
    }
    // after t=31 (pp=1), final h lives in buffer 0
    head_kernel<<<B_, 256>>>(Wlin, blin, out);
}

// round 4
// speedup vs baseline: 1.8282x; 1.8282x over previous
#include <cuda_runtime.h>
#include <cuda_bf16.h>
#include <math.h>
#include <stdint.h>

#define B_   4096
#define T_   32
#define H_   512
#define NG   2048   // 4*H
#define EMB_ 64
#define V_   256
#define O_   64

// ---------------- persistent scratch ----------------
__device__ float d_table[2][V_][NG];                 // per-char gate preactivation (+biases), mma-column layout
__device__ __nv_bfloat16 d_wh[2][NG][H_];            // Whh hi split, rows = mma columns, K contiguous
__device__ __nv_bfloat16 d_wl[2][NG][H_];            // Whh lo split
__device__ __nv_bfloat16 d_hh[2][2][B_ * H_];        // [dir][pp] h hi split, [b][u]
__device__ __nv_bfloat16 d_hl[2][2][B_ * H_];        // [dir][pp] h lo split
__device__ float d_c[2][B_ * H_];                    // cell state, thread-private coalesced layout

// column n (0..2047) -> torch gate row j: gate=((n>>3)&1)*2+(n&1), unit=(n>>4)*4+((n>>1)&3)
__device__ __forceinline__ int jmap2(int n) {
    int gate = (((n >> 3) & 1) << 1) | (n & 1);
    int u    = ((n >> 4) << 2) | ((n >> 1) & 3);
    return gate * H_ + u;
}
__device__ __forceinline__ float sig_f(float x) { return 1.0f / (1.0f + __expf(-x)); }

// ---------------- PTX helpers (plain-target safe: sm_80 baseline) ----------------
__device__ __forceinline__ uint32_t smem_u32(const void* p) {
    uint32_t a;
    asm("{ .reg .u64 t; cvta.to.shared.u64 t, %1; cvt.u32.u64 %0, t; }" : "=r"(a) : "l"(p));
    return a;
}
__device__ __forceinline__ void cp16(uint32_t saddr, const void* g) {
    asm volatile("cp.async.cg.shared.global [%0], [%1], 16;" :: "r"(saddr), "l"(g));
}
#define CP_COMMIT() asm volatile("cp.async.commit_group;" ::: "memory")
#define CP_WAIT0()  asm volatile("cp.async.wait_group 0;" ::: "memory")

__device__ __forceinline__ void ldsm_x4(uint32_t addr, uint32_t* r) {
    asm volatile("ldmatrix.sync.aligned.m8n8.x4.shared.b16 {%0,%1,%2,%3}, [%4];"
        : "=r"(r[0]), "=r"(r[1]), "=r"(r[2]), "=r"(r[3]) : "r"(addr));
}
__device__ __forceinline__ void mma_bf16(float* c, const uint32_t* a, uint32_t b0, uint32_t b1) {
    asm volatile("mma.sync.aligned.m16n8k16.row.col.f32.bf16.bf16.f32 "
        "{%0,%1,%2,%3}, {%4,%5,%6,%7}, {%8,%9}, {%0,%1,%2,%3};"
        : "+f"(c[0]), "+f"(c[1]), "+f"(c[2]), "+f"(c[3])
        : "r"(a[0]), "r"(a[1]), "r"(a[2]), "r"(a[3]), "r"(b0), "r"(b1));
}

// SW128-style XOR swizzle on 128B rows: 16B chunk ^= row&7
__device__ __forceinline__ uint32_t swz(uint32_t base, int row, int cb) {
    uint32_t off = (uint32_t)(row * 128 + cb);
    return base + (off ^ (uint32_t)((row & 7) << 4));
}

// ---------------- SMEM layout ----------------
#define STG_SZ    65536     // per-stage: Ah,Al,Bh,Bl each 16384 (128 rows x 128B)
#define OFF_AH(s) ((s) * STG_SZ + 0)
#define OFF_AL(s) ((s) * STG_SZ + 16384)
#define OFF_BH(s) ((s) * STG_SZ + 32768)
#define OFF_BL(s) ((s) * STG_SZ + 49152)
#define SMEM_TOTAL (2 * STG_SZ)   // 131072
#define HSTG 80                   // h-staging row stride (bytes), 16B aligned, bank-spread

// ---------------- one-off precompute ----------------
__global__ void build_table(const float* __restrict__ emb,
                            const float* __restrict__ Wih1, const float* __restrict__ bih1, const float* __restrict__ bhh1,
                            const float* __restrict__ Wih2, const float* __restrict__ bih2, const float* __restrict__ bhh2) {
    int n   = blockIdx.x * 128 + threadIdx.x;
    int v   = blockIdx.y;
    int dir = blockIdx.z;
    const float* Wih = dir ? Wih2 : Wih1;
    const float* bi  = dir ? bih2 : bih1;
    const float* bh  = dir ? bhh2 : bhh1;
    int j = jmap2(n);
    float s = bi[j] + bh[j];
    const float* e = emb + v * EMB_;
    const float* w = Wih + j * EMB_;
#pragma unroll 16
    for (int k = 0; k < EMB_; k++) s += e[k] * w[k];
    d_table[dir][v][n] = s;
}

__global__ void build_wt(const float* __restrict__ Whh1, const float* __restrict__ Whh2) {
    int k   = blockIdx.x * 128 + threadIdx.x;   // 0..511
    int n   = blockIdx.y;                        // 0..2047
    int dir = blockIdx.z;
    const float* W = dir ? Whh2 : Whh1;
    float w = W[jmap2(n) * H_ + k];
    __nv_bfloat16 wh = __float2bfloat16(w);
    d_wh[dir][n][k] = wh;
    d_wl[dir][n][k] = __float2bfloat16(w - __bfloat162float(wh));
}

__global__ void init_state() {
    int i = blockIdx.x * 256 + threadIdx.x;
    if (i < B_ * H_) {
        __nv_bfloat16 z = __float2bfloat16(0.f);
        d_hh[0][0][i] = z; d_hh[1][0][i] = z;
        d_hl[0][0][i] = z; d_hl[1][0][i] = z;
        d_c[0][i] = 0.f;   d_c[1][i] = 0.f;
    }
}

// ---------------- async stage: one hi/lo tile pair (128 rows x 128B each) ----------------
__device__ __forceinline__ void stage_async(uint32_t sb, uint32_t offH, uint32_t offL,
                                            const __nv_bfloat16* __restrict__ srcH,
                                            const __nv_bfloat16* __restrict__ srcL,
                                            int rowbase, int k0, int tid) {
#pragma unroll
    for (int j = 0; j < 4; j++) {
        int lin = tid + j * 256;      // 0..1023
        int row = lin >> 3;           // 0..127
        int c   = lin & 7;            // 0..7  (8 x 16B = 128B per row)
        uint32_t so = (uint32_t)(row * 128 + c * 16);
        so ^= (uint32_t)((row & 7) << 4);
        const char* gh = (const char*)(srcH + (size_t)(rowbase + row) * H_ + k0) + c * 16;
        const char* gl = (const char*)(srcL + (size_t)(rowbase + row) * H_ + k0) + c * 16;
        cp16(sb + offH + so, gh);
        cp16(sb + offL + so, gl);
    }
}

// ---------------- fused recurrent step on mma.sync tensor cores ----------------
__global__ void __launch_bounds__(256, 1) lstm_step_mma(const int* __restrict__ x, int t, int pp) {
    extern __shared__ __align__(1024) char sm[];
    const int dir  = blockIdx.z;
    const int tcol = dir ? (T_ - 1 - t) : t;
    const int n0   = blockIdx.x * 128;
    const int b0   = blockIdx.y * 128;

    const __nv_bfloat16* __restrict__ hh = d_hh[dir][pp];
    const __nv_bfloat16* __restrict__ hl = d_hl[dir][pp];
    __nv_bfloat16* __restrict__ hh_n = d_hh[dir][pp ^ 1];
    __nv_bfloat16* __restrict__ hl_n = d_hl[dir][pp ^ 1];
    float* __restrict__ cst = d_c[dir];
    const __nv_bfloat16* __restrict__ Wh = &d_wh[dir][0][0];
    const __nv_bfloat16* __restrict__ Wl = &d_wl[dir][0][0];

    const uint32_t sb = smem_u32(sm);
    const int tid  = threadIdx.x;
    const int wid  = tid >> 5;
    const int lane = tid & 31;
    const int wm   = wid >> 1;    // 0..3: 32-row band
    const int wn   = wid & 1;     // 0..1: 64-col band
    const int g    = lane >> 2;
    const int tg   = lane & 3;

    float acc[2][8][4];
#pragma unroll
    for (int i = 0; i < 2; i++)
#pragma unroll
        for (int j = 0; j < 8; j++)
#pragma unroll
            for (int r = 0; r < 4; r++) acc[i][j][r] = 0.f;

    // prologue: stage k-tile 0
    stage_async(sb, OFF_AH(0), OFF_AL(0), hh, hl, b0, 0, tid);
    stage_async(sb, OFF_BH(0), OFF_BL(0), Wh, Wl, n0, 0, tid);
    CP_COMMIT();

    const int lrow  = lane & 15;
    const int lhalf = lane >> 4;

    for (int kt = 0; kt < 8; kt++) {
        CP_WAIT0();
        __syncthreads();
        if (kt < 7) {
            const int nb = (kt + 1) & 1;
            const int k0 = (kt + 1) * 64;
            stage_async(sb, OFF_AH(nb), OFF_AL(nb), hh, hl, b0, k0, tid);
            stage_async(sb, OFF_BH(nb), OFF_BL(nb), Wh, Wl, n0, k0, tid);
            CP_COMMIT();
        }
        const int buf = kt & 1;
        const uint32_t baseAH = sb + OFF_AH(buf), baseAL = sb + OFF_AL(buf);
        const uint32_t baseBH = sb + OFF_BH(buf), baseBL = sb + OFF_BL(buf);
#pragma unroll
        for (int kk = 0; kk < 4; kk++) {
            const int kb = kk * 32 + lhalf * 16;   // byte col of this lane's 16B chunk
            uint32_t ah[2][4], al[2][4];
#pragma unroll
            for (int i = 0; i < 2; i++) {
                ldsm_x4(swz(baseAH, wm * 32 + i * 16 + lrow, kb), ah[i]);
                ldsm_x4(swz(baseAL, wm * 32 + i * 16 + lrow, kb), al[i]);
            }
            uint32_t bh[4][4], bl[4][4];
#pragma unroll
            for (int q = 0; q < 4; q++) {
                ldsm_x4(swz(baseBH, wn * 64 + q * 16 + lrow, kb), bh[q]);
                ldsm_x4(swz(baseBL, wn * 64 + q * 16 + lrow, kb), bl[q]);
            }
#pragma unroll
            for (int i = 0; i < 2; i++)
#pragma unroll
                for (int q = 0; q < 4; q++)
#pragma unroll
                    for (int nb2 = 0; nb2 < 2; nb2++) {
                        float* c = acc[i][q * 2 + nb2];
                        mma_bf16(c, ah[i], bh[q][nb2], bh[q][nb2 + 2]);
                        mma_bf16(c, ah[i], bl[q][nb2], bl[q][nb2 + 2]);
                        mma_bf16(c, al[i], bh[q][nb2], bh[q][nb2 + 2]);
                    }
        }
    }

    // ---------------- epilogue: gates + cell update, all in-register ----------------
    // C frag: c0=D[g][2tg], c1=D[g][2tg+1], c2=D[g+8][2tg], c3=D[g+8][2tg+1]
    // n-block 2jj -> (i,f) cols, n-block 2jj+1 -> (g,o) cols, unit u_l=(wn*4+jj)*4+tg
    const int cbase = (((blockIdx.y * 16 + blockIdx.x) * 256 + tid) << 4);
    float cv[16];
#pragma unroll
    for (int q = 0; q < 4; q++) *(float4*)&cv[q * 4] = *(const float4*)&cst[cbase + q * 4];

#pragma unroll
    for (int i = 0; i < 2; i++) {
        const int r0 = wm * 32 + i * 16 + g;     // local rows r0, r0+8
        const int ch0 = x[(size_t)(b0 + r0) * T_ + tcol];
        const int ch1 = x[(size_t)(b0 + r0 + 8) * T_ + tcol];
        const float* trow0 = &d_table[dir][ch0][n0];
        const float* trow1 = &d_table[dir][ch1][n0];
#pragma unroll
        for (int jj = 0; jj < 4; jj++) {
            const int colIF = wn * 64 + jj * 16 + 2 * tg;   // (i,f) cols; (g,o) at +8
            const int u_l   = (wn * 4 + jj) * 4 + tg;        // local unit 0..31
#pragma unroll
            for (int half = 0; half < 2; half++) {
                const float* trow = half ? trow1 : trow0;
                const float2 tif = *(const float2*)&trow[colIF];
                const float2 tgo = *(const float2*)&trow[colIF + 8];
                float gi = acc[i][jj * 2 + 0][half * 2 + 0] + tif.x;
                float gf = acc[i][jj * 2 + 0][half * 2 + 1] + tif.y;
                float gg = acc[i][jj * 2 + 1][half * 2 + 0] + tgo.x;
                float go = acc[i][jj * 2 + 1][half * 2 + 1] + tgo.y;
                const int idx = i * 8 + jj * 2 + half;
                float c_new = sig_f(gf) * cv[idx] + sig_f(gi) * tanhf(gg);
                cv[idx] = c_new;
                const float hv = sig_f(go) * tanhf(c_new);
                const __nv_bfloat16 hb = __float2bfloat16(hv);
                const __nv_bfloat16 lb = __float2bfloat16(hv - __bfloat162float(hb));
                const int rl = r0 + half * 8;    // local row
                // stage into smem (hi at OFF_AH(0), lo at OFF_AL(0)); buf0 is dead after kt=6
                *(__nv_bfloat16*)(sm + OFF_AH(0) + rl * HSTG + u_l * 2) = hb;
                *(__nv_bfloat16*)(sm + OFF_AL(0) + rl * HSTG + u_l * 2) = lb;
            }
        }
    }
#pragma unroll
    for (int q = 0; q < 4; q++) *(float4*)&cst[cbase + q * 4] = *(const float4*)&cv[q * 4];

    __syncthreads();
    // coalesced h store: 128 rows x 32 units (64B/row) per split
    const int u0 = n0 >> 2;   // CTA's unit base (32 units)
#pragma unroll
    for (int it = 0; it < 2; it++) {
        const int idx = tid + it * 256;
        const int row = idx >> 2;
        const int q   = idx & 3;
        uint4 vh = *(const uint4*)(sm + OFF_AH(0) + row * HSTG + q * 16);
        uint4 vl = *(const uint4*)(sm + OFF_AL(0) + row * HSTG + q * 16);
        *(uint4*)((char*)(hh_n + (size_t)(b0 + row) * H_ + u0) + q * 16) = vh;
        *(uint4*)((char*)(hl_n + (size_t)(b0 + row) * H_ + u0) + q * 16) = vl;
    }
}

// ---------------- classifier head + softmax ----------------
__global__ void head_kernel(const float* __restrict__ Wlin, const float* __restrict__ blin,
                            float* __restrict__ out) {
    const int b    = blockIdx.x;
    const int tid  = threadIdx.x;
    const int w    = tid >> 5;
    const int lane = tid & 31;

    __shared__ __align__(16) float hrow[1024];
    __shared__ float lg[O_];
    __shared__ float red[2];

    for (int i = tid; i < H_; i += 256) {
        hrow[i]      = __bfloat162float(d_hh[0][0][b * H_ + i]) + __bfloat162float(d_hl[0][0][b * H_ + i]);
        hrow[H_ + i] = __bfloat162float(d_hh[1][0][b * H_ + i]) + __bfloat162float(d_hl[1][0][b * H_ + i]);
    }
    __syncthreads();

    const float4* hr4 = (const float4*)hrow;
#pragma unroll
    for (int oo = 0; oo < 8; oo++) {
        const int o = w * 8 + oo;
        const float4* wl = (const float4*)(Wlin + o * 1024);
        float s = 0.f;
#pragma unroll
        for (int it = 0; it < 8; it++) {
            float4 a  = hr4[it * 32 + lane];
            float4 bw = wl[it * 32 + lane];
            s += a.x * bw.x + a.y * bw.y + a.z * bw.z + a.w * bw.w;
        }
#pragma unroll
        for (int off = 16; off; off >>= 1) s += __shfl_down_sync(0xffffffffu, s, off);
        if (lane == 0) lg[o] = s + blin[o];
    }
    __syncthreads();

    if (tid == 0) {
        float m = lg[0];
        for (int i = 1; i < O_; i++) m = fmaxf(m, lg[i]);
        red[0] = m;
    }
    __syncthreads();
    if (tid < O_) lg[tid] = expf(lg[tid] - red[0]);
    __syncthreads();
    if (tid == 0) {
        float s = 0.f;
        for (int i = 0; i < O_; i++) s += lg[i];
        red[1] = 1.0f / s;
    }
    __syncthreads();
    if (tid < O_) out[b * O_ + tid] = lg[tid] * red[1];
}

// ---------------- launch ----------------
extern "C" void kernel_launch(void* const* d_in, const int* in_sizes, int n_in,
                              void* d_out, int out_size) {
    const int*   x    = (const int*)d_in[0];
    const float* emb  = (const float*)d_in[2];
    const float* Wih1 = (const float*)d_in[3];
    const float* Whh1 = (const float*)d_in[4];
    const float* bih1 = (const float*)d_in[5];
    const float* bhh1 = (const float*)d_in[6];
    const float* Wih2 = (const float*)d_in[7];
    const float* Whh2 = (const float*)d_in[8];
    const float* bih2 = (const float*)d_in[9];
    const float* bhh2 = (const float*)d_in[10];
    const float* Wlin = (const float*)d_in[11];
    const float* blin = (const float*)d_in[12];
    float* out = (float*)d_out;

    cudaFuncSetAttribute(lstm_step_mma, cudaFuncAttributeMaxDynamicSharedMemorySize, SMEM_TOTAL);

    dim3 g1(NG / 128, V_, 2);
    build_table<<<g1, 128>>>(emb, Wih1, bih1, bhh1, Wih2, bih2, bhh2);
    dim3 g2(H_ / 128, NG, 2);
    build_wt<<<g2, 128>>>(Whh1, Whh2);
    init_state<<<(B_ * H_ + 255) / 256, 256>>>();

    dim3 gs(NG / 128, B_ / 128, 2);   // (16, 32, 2) = 1024 CTAs
    for (int t = 0; t < T_; t++) {
        lstm_step_mma<<<gs, 256, SMEM_TOTAL>>>(x, t, t & 1);
    }
    head_kernel<<<B_, 256>>>(Wlin, blin, out);
}

// round 5
// speedup vs baseline: 1.9297x; 1.0556x over previous
#include <cuda_runtime.h>
#include <cuda_bf16.h>
#include <math.h>
#include <stdint.h>

#define B_   4096
#define T_   32
#define H_   512
#define NG   2048   // 4*H
#define EMB_ 64
#define V_   256
#define O_   64

// ---------------- persistent scratch ----------------
__device__ float d_table[2][V_][NG];                 // per-char gate preactivation (+biases), mma-column layout
__device__ __nv_bfloat16 d_wh[2][NG][H_];            // Whh hi split, rows = mma columns, K contiguous
__device__ __nv_bfloat16 d_wl[2][NG][H_];            // Whh lo split
__device__ __nv_bfloat16 d_hh[2][2][B_ * H_];        // [dir][pp] h hi split
__device__ __nv_bfloat16 d_hl[2][2][B_ * H_];        // [dir][pp] h lo split
__device__ float d_c[2][B_ * H_];                    // cell state, thread-private coalesced layout

// column n (0..2047) -> torch gate row j
__device__ __forceinline__ int jmap2(int n) {
    int gate = (((n >> 3) & 1) << 1) | (n & 1);
    int u    = ((n >> 4) << 2) | ((n >> 1) & 3);
    return gate * H_ + u;
}
__device__ __forceinline__ float sig_f(float x) { return 1.0f / (1.0f + __expf(-x)); }

// ---------------- PTX helpers (plain-target safe) ----------------
__device__ __forceinline__ uint32_t smem_u32(const void* p) {
    uint32_t a;
    asm("{ .reg .u64 t; cvta.to.shared.u64 t, %1; cvt.u32.u64 %0, t; }" : "=r"(a) : "l"(p));
    return a;
}
__device__ __forceinline__ void cp16(uint32_t saddr, const void* g) {
    asm volatile("cp.async.cg.shared.global [%0], [%1], 16;" :: "r"(saddr), "l"(g));
}
#define CP_COMMIT() asm volatile("cp.async.commit_group;" ::: "memory")
#define CP_WAIT0()  asm volatile("cp.async.wait_group 0;" ::: "memory")

__device__ __forceinline__ void ldsm_x4(uint32_t addr, uint32_t* r) {
    asm volatile("ldmatrix.sync.aligned.m8n8.x4.shared.b16 {%0,%1,%2,%3}, [%4];"
        : "=r"(r[0]), "=r"(r[1]), "=r"(r[2]), "=r"(r[3]) : "r"(addr));
}
__device__ __forceinline__ void mma_bf16(float* c, const uint32_t* a, uint32_t b0, uint32_t b1) {
    asm volatile("mma.sync.aligned.m16n8k16.row.col.f32.bf16.bf16.f32 "
        "{%0,%1,%2,%3}, {%4,%5,%6,%7}, {%8,%9}, {%0,%1,%2,%3};"
        : "+f"(c[0]), "+f"(c[1]), "+f"(c[2]), "+f"(c[3])
        : "r"(a[0]), "r"(a[1]), "r"(a[2]), "r"(a[3]), "r"(b0), "r"(b1));
}

// 128B-row XOR swizzle
__device__ __forceinline__ uint32_t swz(uint32_t base, int row, int cb) {
    uint32_t off = (uint32_t)(row * 128 + cb);
    return base + (off ^ (uint32_t)((row & 7) << 4));
}

// ---------------- SMEM layout: CTA 256x128, K-tile 64 ----------------
// per stage: Ah 32768 (256 rows x 128B), Al 32768, Bh 16384 (128 rows), Bl 16384 = 98304
#define STG_SZ    98304
#define OFF_AH(s) ((s) * STG_SZ + 0)
#define OFF_AL(s) ((s) * STG_SZ + 32768)
#define OFF_BH(s) ((s) * STG_SZ + 65536)
#define OFF_BL(s) ((s) * STG_SZ + 81920)
#define SMEM_TOTAL (2 * STG_SZ)   // 196608
#define HSTG 80                   // h-staging row stride (bytes)

// ---------------- one-off precompute ----------------
__global__ void build_table(const float* __restrict__ emb,
                            const float* __restrict__ Wih1, const float* __restrict__ bih1, const float* __restrict__ bhh1,
                            const float* __restrict__ Wih2, const float* __restrict__ bih2, const float* __restrict__ bhh2) {
    int n   = blockIdx.x * 128 + threadIdx.x;
    int v   = blockIdx.y;
    int dir = blockIdx.z;
    const float* Wih = dir ? Wih2 : Wih1;
    const float* bi  = dir ? bih2 : bih1;
    const float* bh  = dir ? bhh2 : bhh1;
    int j = jmap2(n);
    float s = bi[j] + bh[j];
    const float* e = emb + v * EMB_;
    const float* w = Wih + j * EMB_;
#pragma unroll 16
    for (int k = 0; k < EMB_; k++) s += e[k] * w[k];
    d_table[dir][v][n] = s;
}

__global__ void build_wt(const float* __restrict__ Whh1, const float* __restrict__ Whh2) {
    int k   = blockIdx.x * 128 + threadIdx.x;
    int n   = blockIdx.y;
    int dir = blockIdx.z;
    const float* W = dir ? Whh2 : Whh1;
    float w = W[jmap2(n) * H_ + k];
    __nv_bfloat16 wh = __float2bfloat16(w);
    d_wh[dir][n][k] = wh;
    d_wl[dir][n][k] = __float2bfloat16(w - __bfloat162float(wh));
}

__global__ void init_state() {
    int i = blockIdx.x * 256 + threadIdx.x;
    if (i < B_ * H_) {
        __nv_bfloat16 z = __float2bfloat16(0.f);
        d_hh[0][0][i] = z; d_hh[1][0][i] = z;
        d_hl[0][0][i] = z; d_hl[1][0][i] = z;
        d_c[0][i] = 0.f;   d_c[1][i] = 0.f;
    }
}

// ---------------- async stage (generic row count; 512 threads) ----------------
template<int ROWS>
__device__ __forceinline__ void stage_async(uint32_t sb, uint32_t offH, uint32_t offL,
                                            const __nv_bfloat16* __restrict__ srcH,
                                            const __nv_bfloat16* __restrict__ srcL,
                                            int rowbase, int k0, int tid) {
    constexpr int ITERS = (ROWS * 8) / 512;
#pragma unroll
    for (int j = 0; j < ITERS; j++) {
        int lin = tid + j * 512;
        int row = lin >> 3;
        int c   = lin & 7;
        uint32_t so = (uint32_t)(row * 128 + c * 16);
        so ^= (uint32_t)((row & 7) << 4);
        const char* gh = (const char*)(srcH + (size_t)(rowbase + row) * H_ + k0) + c * 16;
        const char* gl = (const char*)(srcL + (size_t)(rowbase + row) * H_ + k0) + c * 16;
        cp16(sb + offH + so, gh);
        cp16(sb + offL + so, gl);
    }
}

// ---------------- fused recurrent step on mma.sync tensor cores ----------------
// CTA tile 256(M) x 128(N), 512 threads = 16 warps (8 row-bands x 2 col-bands)
__global__ void __launch_bounds__(512, 1) lstm_step_mma(const int* __restrict__ x, int t, int pp) {
    extern __shared__ __align__(1024) char sm[];
    const int dir  = blockIdx.z;
    const int tcol = dir ? (T_ - 1 - t) : t;
    const int n0   = blockIdx.x * 128;
    const int b0   = blockIdx.y * 256;

    const __nv_bfloat16* __restrict__ hh = d_hh[dir][pp];
    const __nv_bfloat16* __restrict__ hl = d_hl[dir][pp];
    __nv_bfloat16* __restrict__ hh_n = d_hh[dir][pp ^ 1];
    __nv_bfloat16* __restrict__ hl_n = d_hl[dir][pp ^ 1];
    float* __restrict__ cst = d_c[dir];
    const __nv_bfloat16* __restrict__ Wh = &d_wh[dir][0][0];
    const __nv_bfloat16* __restrict__ Wl = &d_wl[dir][0][0];

    const uint32_t sb = smem_u32(sm);
    const int tid  = threadIdx.x;
    const int wid  = tid >> 5;
    const int lane = tid & 31;
    const int wm   = wid >> 1;    // 0..7: 32-row band
    const int wn   = wid & 1;     // 0..1: 64-col band
    const int g    = lane >> 2;
    const int tg   = lane & 3;

    float acc[2][8][4];
#pragma unroll
    for (int i = 0; i < 2; i++)
#pragma unroll
        for (int j = 0; j < 8; j++)
#pragma unroll
            for (int r = 0; r < 4; r++) acc[i][j][r] = 0.f;

    // prologue: stage k-tile 0
    stage_async<256>(sb, OFF_AH(0), OFF_AL(0), hh, hl, b0, 0, tid);
    stage_async<128>(sb, OFF_BH(0), OFF_BL(0), Wh, Wl, n0, 0, tid);
    CP_COMMIT();

    const int lrow  = lane & 15;
    const int lhalf = lane >> 4;

    for (int kt = 0; kt < 8; kt++) {
        CP_WAIT0();
        __syncthreads();
        if (kt < 7) {
            const int nb = (kt + 1) & 1;
            const int k0 = (kt + 1) * 64;
            stage_async<256>(sb, OFF_AH(nb), OFF_AL(nb), hh, hl, b0, k0, tid);
            stage_async<128>(sb, OFF_BH(nb), OFF_BL(nb), Wh, Wl, n0, k0, tid);
            CP_COMMIT();
        }
        const int buf = kt & 1;
        const uint32_t baseAH = sb + OFF_AH(buf), baseAL = sb + OFF_AL(buf);
        const uint32_t baseBH = sb + OFF_BH(buf), baseBL = sb + OFF_BL(buf);
#pragma unroll
        for (int kk = 0; kk < 4; kk++) {
            const int kb = kk * 32 + lhalf * 16;
            uint32_t af[2][4], bf[4][4];
            // ---- product 1: hi(A) x hi(B) ----
#pragma unroll
            for (int i = 0; i < 2; i++)
                ldsm_x4(swz(baseAH, wm * 32 + i * 16 + lrow, kb), af[i]);
#pragma unroll
            for (int q = 0; q < 4; q++)
                ldsm_x4(swz(baseBH, wn * 64 + q * 16 + lrow, kb), bf[q]);
#pragma unroll
            for (int i = 0; i < 2; i++)
#pragma unroll
                for (int q = 0; q < 4; q++)
#pragma unroll
                    for (int nb2 = 0; nb2 < 2; nb2++)
                        mma_bf16(acc[i][q * 2 + nb2], af[i], bf[q][nb2], bf[q][nb2 + 2]);
            // ---- product 2: lo(A) x hi(B) (reload A frags only) ----
#pragma unroll
            for (int i = 0; i < 2; i++)
                ldsm_x4(swz(baseAL, wm * 32 + i * 16 + lrow, kb), af[i]);
#pragma unroll
            for (int i = 0; i < 2; i++)
#pragma unroll
                for (int q = 0; q < 4; q++)
#pragma unroll
                    for (int nb2 = 0; nb2 < 2; nb2++)
                        mma_bf16(acc[i][q * 2 + nb2], af[i], bf[q][nb2], bf[q][nb2 + 2]);
            // ---- product 3: hi(A) x lo(B) (reload both) ----
#pragma unroll
            for (int i = 0; i < 2; i++)
                ldsm_x4(swz(baseAH, wm * 32 + i * 16 + lrow, kb), af[i]);
#pragma unroll
            for (int q = 0; q < 4; q++)
                ldsm_x4(swz(baseBL, wn * 64 + q * 16 + lrow, kb), bf[q]);
#pragma unroll
            for (int i = 0; i < 2; i++)
#pragma unroll
                for (int q = 0; q < 4; q++)
#pragma unroll
                    for (int nb2 = 0; nb2 < 2; nb2++)
                        mma_bf16(acc[i][q * 2 + nb2], af[i], bf[q][nb2], bf[q][nb2 + 2]);
        }
    }

    // ---------------- epilogue: gates + cell update, in-register ----------------
    const int cbase = (((blockIdx.y * 16 + blockIdx.x) * 512 + tid) << 4);
    float cv[16];
#pragma unroll
    for (int q = 0; q < 4; q++) *(float4*)&cv[q * 4] = *(const float4*)&cst[cbase + q * 4];

#pragma unroll
    for (int i = 0; i < 2; i++) {
        const int r0 = wm * 32 + i * 16 + g;     // local rows r0, r0+8
        const int ch0 = x[(size_t)(b0 + r0) * T_ + tcol];
        const int ch1 = x[(size_t)(b0 + r0 + 8) * T_ + tcol];
        const float* trow0 = &d_table[dir][ch0][n0];
        const float* trow1 = &d_table[dir][ch1][n0];
#pragma unroll
        for (int jj = 0; jj < 4; jj++) {
            const int colIF = wn * 64 + jj * 16 + 2 * tg;   // (i,f) cols; (g,o) at +8
            const int u_l   = (wn * 4 + jj) * 4 + tg;        // local unit 0..31
#pragma unroll
            for (int half = 0; half < 2; half++) {
                const float* trow = half ? trow1 : trow0;
                const float2 tif = *(const float2*)&trow[colIF];
                const float2 tgo = *(const float2*)&trow[colIF + 8];
                float gi = acc[i][jj * 2 + 0][half * 2 + 0] + tif.x;
                float gf = acc[i][jj * 2 + 0][half * 2 + 1] + tif.y;
                float gg = acc[i][jj * 2 + 1][half * 2 + 0] + tgo.x;
                float go = acc[i][jj * 2 + 1][half * 2 + 1] + tgo.y;
                const int idx = i * 8 + jj * 2 + half;
                float c_new = sig_f(gf) * cv[idx] + sig_f(gi) * tanhf(gg);
                cv[idx] = c_new;
                const float hv = sig_f(go) * tanhf(c_new);
                const __nv_bfloat16 hb = __float2bfloat16(hv);
                const __nv_bfloat16 lb = __float2bfloat16(hv - __bfloat162float(hb));
                const int rl = r0 + half * 8;    // local row 0..255
                *(__nv_bfloat16*)(sm + OFF_AH(0) + rl * HSTG + u_l * 2) = hb;
                *(__nv_bfloat16*)(sm + OFF_AL(0) + rl * HSTG + u_l * 2) = lb;
            }
        }
    }
#pragma unroll
    for (int q = 0; q < 4; q++) *(float4*)&cst[cbase + q * 4] = *(const float4*)&cv[q * 4];

    __syncthreads();
    // coalesced h store: 256 rows x 32 units (64B/row) per split
    const int u0 = n0 >> 2;
#pragma unroll
    for (int it = 0; it < 2; it++) {
        const int idx = tid + it * 512;
        const int row = idx >> 2;
        const int q   = idx & 3;
        uint4 vh = *(const uint4*)(sm + OFF_AH(0) + row * HSTG + q * 16);
        uint4 vl = *(const uint4*)(sm + OFF_AL(0) + row * HSTG + q * 16);
        *(uint4*)((char*)(hh_n + (size_t)(b0 + row) * H_ + u0) + q * 16) = vh;
        *(uint4*)((char*)(hl_n + (size_t)(b0 + row) * H_ + u0) + q * 16) = vl;
    }
}

// ---------------- classifier head + softmax ----------------
__global__ void head_kernel(const float* __restrict__ Wlin, const float* __restrict__ blin,
                            float* __restrict__ out) {
    const int b    = blockIdx.x;
    const int tid  = threadIdx.x;
    const int w    = tid >> 5;
    const int lane = tid & 31;

    __shared__ __align__(16) float hrow[1024];
    __shared__ float lg[O_];
    __shared__ float red[2];

    for (int i = tid; i < H_; i += 256) {
        hrow[i]      = __bfloat162float(d_hh[0][0][b * H_ + i]) + __bfloat162float(d_hl[0][0][b * H_ + i]);
        hrow[H_ + i] = __bfloat162float(d_hh[1][0][b * H_ + i]) + __bfloat162float(d_hl[1][0][b * H_ + i]);
    }
    __syncthreads();

    const float4* hr4 = (const float4*)hrow;
#pragma unroll
    for (int oo = 0; oo < 8; oo++) {
        const int o = w * 8 + oo;
        const float4* wl = (const float4*)(Wlin + o * 1024);
        float s = 0.f;
#pragma unroll
        for (int it = 0; it < 8; it++) {
            float4 a  = hr4[it * 32 + lane];
            float4 bw = wl[it * 32 + lane];
            s += a.x * bw.x + a.y * bw.y + a.z * bw.z + a.w * bw.w;
        }
#pragma unroll
        for (int off = 16; off; off >>= 1) s += __shfl_down_sync(0xffffffffu, s, off);
        if (lane == 0) lg[o] = s + blin[o];
    }
    __syncthreads();

    if (tid == 0) {
        float m = lg[0];
        for (int i = 1; i < O_; i++) m = fmaxf(m, lg[i]);
        red[0] = m;
    }
    __syncthreads();
    if (tid < O_) lg[tid] = expf(lg[tid] - red[0]);
    __syncthreads();
    if (tid == 0) {
        float s = 0.f;
        for (int i = 0; i < O_; i++) s += lg[i];
        red[1] = 1.0f / s;
    }
    __syncthreads();
    if (tid < O_) out[b * O_ + tid] = lg[tid] * red[1];
}

// ---------------- launch ----------------
extern "C" void kernel_launch(void* const* d_in, const int* in_sizes, int n_in,
                              void* d_out, int out_size) {
    const int*   x    = (const int*)d_in[0];
    const float* emb  = (const float*)d_in[2];
    const float* Wih1 = (const float*)d_in[3];
    const float* Whh1 = (const float*)d_in[4];
    const float* bih1 = (const float*)d_in[5];
    const float* bhh1 = (const float*)d_in[6];
    const float* Wih2 = (const float*)d_in[7];
    const float* Whh2 = (const float*)d_in[8];
    const float* bih2 = (const float*)d_in[9];
    const float* bhh2 = (const float*)d_in[10];
    const float* Wlin = (const float*)d_in[11];
    const float* blin = (const float*)d_in[12];
    float* out = (float*)d_out;

    cudaFuncSetAttribute(lstm_step_mma, cudaFuncAttributeMaxDynamicSharedMemorySize, SMEM_TOTAL);

    dim3 g1(NG / 128, V_, 2);
    build_table<<<g1, 128>>>(emb, Wih1, bih1, bhh1, Wih2, bih2, bhh2);
    dim3 g2(H_ / 128, NG, 2);
    build_wt<<<g2, 128>>>(Whh1, Whh2);
    init_state<<<(B_ * H_ + 255) / 256, 256>>>();

    dim3 gs(NG / 128, B_ / 256, 2);   // (16, 16, 2) = 512 CTAs
    for (int t = 0; t < T_; t++) {
        lstm_step_mma<<<gs, 512, SMEM_TOTAL>>>(x, t, t & 1);
    }
    head_kernel<<<B_, 256>>>(Wlin, blin, out);
}

// round 6
// speedup vs baseline: 2.1455x; 1.1118x over previous
#include <cuda_runtime.h>
#include <cuda_bf16.h>
#include <math.h>
#include <stdint.h>

#define B_   4096
#define T_   32
#define H_   512
#define NG   2048   // 4*H
#define EMB_ 64
#define V_   256
#define O_   64

// ---------------- persistent scratch ----------------
__device__ float d_table[2][V_][NG];                 // per-char gate preactivation (+biases), mma-column layout
__device__ __nv_bfloat16 d_wh[2][NG][H_];            // Whh hi split, rows = mma columns, K contiguous
__device__ __nv_bfloat16 d_wl[2][NG][H_];            // Whh lo split
__device__ __nv_bfloat16 d_hh[2][2][B_ * H_];        // [dir][pp] h hi split
__device__ __nv_bfloat16 d_hl[2][2][B_ * H_];        // [dir][pp] h lo split
__device__ float d_c[2][B_ * H_];                    // cell state, thread-private coalesced layout

// column n (0..2047) -> torch gate row j
__device__ __forceinline__ int jmap2(int n) {
    int gate = (((n >> 3) & 1) << 1) | (n & 1);
    int u    = ((n >> 4) << 2) | ((n >> 1) & 3);
    return gate * H_ + u;
}
__device__ __forceinline__ float sig_f(float x) { return 1.0f / (1.0f + __expf(-x)); }

// ---------------- PTX helpers (plain-target safe) ----------------
__device__ __forceinline__ uint32_t smem_u32(const void* p) {
    uint32_t a;
    asm("{ .reg .u64 t; cvta.to.shared.u64 t, %1; cvt.u32.u64 %0, t; }" : "=r"(a) : "l"(p));
    return a;
}
__device__ __forceinline__ void cp16(uint32_t saddr, const void* g) {
    asm volatile("cp.async.cg.shared.global [%0], [%1], 16;" :: "r"(saddr), "l"(g));
}
#define CP_COMMIT() asm volatile("cp.async.commit_group;" ::: "memory")
#define CP_WAIT0()  asm volatile("cp.async.wait_group 0;" ::: "memory")
#define CP_WAIT1()  asm volatile("cp.async.wait_group 1;" ::: "memory")

__device__ __forceinline__ void ldsm_x4(uint32_t addr, uint32_t* r) {
    asm volatile("ldmatrix.sync.aligned.m8n8.x4.shared.b16 {%0,%1,%2,%3}, [%4];"
        : "=r"(r[0]), "=r"(r[1]), "=r"(r[2]), "=r"(r[3]) : "r"(addr));
}
__device__ __forceinline__ void mma_bf16(float* c, const uint32_t* a, uint32_t b0, uint32_t b1) {
    asm volatile("mma.sync.aligned.m16n8k16.row.col.f32.bf16.bf16.f32 "
        "{%0,%1,%2,%3}, {%4,%5,%6,%7}, {%8,%9}, {%0,%1,%2,%3};"
        : "+f"(c[0]), "+f"(c[1]), "+f"(c[2]), "+f"(c[3])
        : "r"(a[0]), "r"(a[1]), "r"(a[2]), "r"(a[3]), "r"(b0), "r"(b1));
}

// 64B-row layout, conflict-free swizzle: 16B chunk index ^= (row>>1)&3
__device__ __forceinline__ uint32_t swz32(uint32_t base, int row, int cb) {
    uint32_t chunk = ((uint32_t)cb >> 4) ^ (((uint32_t)row >> 1) & 3u);
    return base + (uint32_t)row * 64 + chunk * 16;
}

// ---------------- SMEM layout: CTA 128x128, K-tile 32, 3 stages ----------------
// per tile: 128 rows x 64B = 8192; per stage Ah,Al,Bh,Bl = 32768
#define TILE_SZ  8192
#define STG_SZ   32768
#define NSTG     3
#define OFF_AH(s) ((s) * STG_SZ + 0)
#define OFF_AL(s) ((s) * STG_SZ + TILE_SZ)
#define OFF_BH(s) ((s) * STG_SZ + 2 * TILE_SZ)
#define OFF_BL(s) ((s) * STG_SZ + 3 * TILE_SZ)
#define SMEM_TOTAL (NSTG * STG_SZ)   // 98304
#define HSTG 80                      // h-staging row stride (bytes)

// ---------------- one-off precompute ----------------
__global__ void build_table(const float* __restrict__ emb,
                            const float* __restrict__ Wih1, const float* __restrict__ bih1, const float* __restrict__ bhh1,
                            const float* __restrict__ Wih2, const float* __restrict__ bih2, const float* __restrict__ bhh2) {
    int n   = blockIdx.x * 128 + threadIdx.x;
    int v   = blockIdx.y;
    int dir = blockIdx.z;
    const float* Wih = dir ? Wih2 : Wih1;
    const float* bi  = dir ? bih2 : bih1;
    const float* bh  = dir ? bhh2 : bhh1;
    int j = jmap2(n);
    float s = bi[j] + bh[j];
    const float* e = emb + v * EMB_;
    const float* w = Wih + j * EMB_;
#pragma unroll 16
    for (int k = 0; k < EMB_; k++) s += e[k] * w[k];
    d_table[dir][v][n] = s;
}

__global__ void build_wt(const float* __restrict__ Whh1, const float* __restrict__ Whh2) {
    int k   = blockIdx.x * 128 + threadIdx.x;
    int n   = blockIdx.y;
    int dir = blockIdx.z;
    const float* W = dir ? Whh2 : Whh1;
    float w = W[jmap2(n) * H_ + k];
    __nv_bfloat16 wh = __float2bfloat16(w);
    d_wh[dir][n][k] = wh;
    d_wl[dir][n][k] = __float2bfloat16(w - __bfloat162float(wh));
}

__global__ void init_state() {
    int i = blockIdx.x * 256 + threadIdx.x;
    if (i < B_ * H_) {
        __nv_bfloat16 z = __float2bfloat16(0.f);
        d_hh[0][0][i] = z; d_hh[1][0][i] = z;
        d_hl[0][0][i] = z; d_hl[1][0][i] = z;
        d_c[0][i] = 0.f;   d_c[1][i] = 0.f;
    }
}

// ---------------- async stage: one 128x32 bf16 tile (256 threads) ----------------
__device__ __forceinline__ void stage_tile(uint32_t sdst,
                                           const __nv_bfloat16* __restrict__ src,
                                           int rowbase, int k0, int tid) {
#pragma unroll
    for (int j = 0; j < 2; j++) {
        int lin = tid + j * 256;              // 0..511
        int row = lin >> 2;                   // 0..127
        int c   = lin & 3;                    // 16B chunk within 64B row
        uint32_t chunk = (uint32_t)c ^ (((uint32_t)row >> 1) & 3u);
        cp16(sdst + (uint32_t)row * 64 + chunk * 16,
             (const char*)(src + (size_t)(rowbase + row) * H_ + k0) + c * 16);
    }
}

// ---------------- fused recurrent step on mma.sync tensor cores ----------------
// CTA tile 128(M) x 128(N), K-tile 32, 256 threads, 2 CTAs/SM
__global__ void __launch_bounds__(256, 2) lstm_step_mma(const int* __restrict__ x, int t, int pp) {
    extern __shared__ __align__(1024) char sm[];
    const int dir  = blockIdx.z;
    const int tcol = dir ? (T_ - 1 - t) : t;
    const int n0   = blockIdx.x * 128;
    const int b0   = blockIdx.y * 128;

    const __nv_bfloat16* __restrict__ hh = d_hh[dir][pp];
    const __nv_bfloat16* __restrict__ hl = d_hl[dir][pp];
    __nv_bfloat16* __restrict__ hh_n = d_hh[dir][pp ^ 1];
    __nv_bfloat16* __restrict__ hl_n = d_hl[dir][pp ^ 1];
    float* __restrict__ cst = d_c[dir];
    const __nv_bfloat16* __restrict__ Wh = &d_wh[dir][0][0];
    const __nv_bfloat16* __restrict__ Wl = &d_wl[dir][0][0];

    const uint32_t sb = smem_u32(sm);
    const int tid  = threadIdx.x;
    const int wid  = tid >> 5;
    const int lane = tid & 31;
    const int wm   = wid >> 1;    // 0..3: 32-row band
    const int wn   = wid & 1;     // 0..1: 64-col band
    const int g    = lane >> 2;
    const int tg   = lane & 3;

    float acc[2][8][4];
#pragma unroll
    for (int i = 0; i < 2; i++)
#pragma unroll
        for (int j = 0; j < 8; j++)
#pragma unroll
            for (int r = 0; r < 4; r++) acc[i][j][r] = 0.f;

    // prologue: stage k-tiles 0 and 1
    stage_tile(sb + OFF_AH(0), hh, b0, 0, tid);
    stage_tile(sb + OFF_AL(0), hl, b0, 0, tid);
    stage_tile(sb + OFF_BH(0), Wh, n0, 0, tid);
    stage_tile(sb + OFF_BL(0), Wl, n0, 0, tid);
    CP_COMMIT();
    stage_tile(sb + OFF_AH(1), hh, b0, 32, tid);
    stage_tile(sb + OFF_AL(1), hl, b0, 32, tid);
    stage_tile(sb + OFF_BH(1), Wh, n0, 32, tid);
    stage_tile(sb + OFF_BL(1), Wl, n0, 32, tid);
    CP_COMMIT();

    const int lrow  = lane & 15;
    const int lhalf = lane >> 4;

    for (int kt = 0; kt < 16; kt++) {
        if (kt < 15) { CP_WAIT1(); } else { CP_WAIT0(); }
        __syncthreads();
        if (kt + 2 < 16) {
            const int nb = (kt + 2) % NSTG;
            const int k0 = (kt + 2) * 32;
            stage_tile(sb + OFF_AH(nb), hh, b0, k0, tid);
            stage_tile(sb + OFF_AL(nb), hl, b0, k0, tid);
            stage_tile(sb + OFF_BH(nb), Wh, n0, k0, tid);
            stage_tile(sb + OFF_BL(nb), Wl, n0, k0, tid);
            CP_COMMIT();
        }
        const int buf = kt % NSTG;
        const uint32_t baseAH = sb + OFF_AH(buf), baseAL = sb + OFF_AL(buf);
        const uint32_t baseBH = sb + OFF_BH(buf), baseBL = sb + OFF_BL(buf);
#pragma unroll
        for (int kk = 0; kk < 2; kk++) {
            const int kb = kk * 32 + lhalf * 16;
            uint32_t af[2][4], bf4[4][4];
            // ---- product 1: lo(A) x hi(B) ----
#pragma unroll
            for (int i = 0; i < 2; i++)
                ldsm_x4(swz32(baseAL, wm * 32 + i * 16 + lrow, kb), af[i]);
#pragma unroll
            for (int q = 0; q < 4; q++)
                ldsm_x4(swz32(baseBH, wn * 64 + q * 16 + lrow, kb), bf4[q]);
#pragma unroll
            for (int i = 0; i < 2; i++)
#pragma unroll
                for (int q = 0; q < 4; q++)
#pragma unroll
                    for (int nb2 = 0; nb2 < 2; nb2++)
                        mma_bf16(acc[i][q * 2 + nb2], af[i], bf4[q][nb2], bf4[q][nb2 + 2]);
            // ---- product 2: hi(A) x hi(B) (reload A only) ----
#pragma unroll
            for (int i = 0; i < 2; i++)
                ldsm_x4(swz32(baseAH, wm * 32 + i * 16 + lrow, kb), af[i]);
#pragma unroll
            for (int i = 0; i < 2; i++)
#pragma unroll
                for (int q = 0; q < 4; q++)
#pragma unroll
                    for (int nb2 = 0; nb2 < 2; nb2++)
                        mma_bf16(acc[i][q * 2 + nb2], af[i], bf4[q][nb2], bf4[q][nb2 + 2]);
            // ---- product 3: hi(A) x lo(B) (reload B only) ----
#pragma unroll
            for (int q = 0; q < 4; q++)
                ldsm_x4(swz32(baseBL, wn * 64 + q * 16 + lrow, kb), bf4[q]);
#pragma unroll
            for (int i = 0; i < 2; i++)
#pragma unroll
                for (int q = 0; q < 4; q++)
#pragma unroll
                    for (int nb2 = 0; nb2 < 2; nb2++)
                        mma_bf16(acc[i][q * 2 + nb2], af[i], bf4[q][nb2], bf4[q][nb2 + 2]);
        }
    }

    __syncthreads();   // all mma smem reads retired before staging reuse of buf 0

    // ---------------- epilogue: gates + cell update, in-register ----------------
    const int cbase = (((blockIdx.y * 16 + blockIdx.x) * 256 + tid) << 4);
    float cv[16];
#pragma unroll
    for (int q = 0; q < 4; q++) *(float4*)&cv[q * 4] = *(const float4*)&cst[cbase + q * 4];

#pragma unroll
    for (int i = 0; i < 2; i++) {
        const int r0 = wm * 32 + i * 16 + g;     // local rows r0, r0+8
        const int ch0 = x[(size_t)(b0 + r0) * T_ + tcol];
        const int ch1 = x[(size_t)(b0 + r0 + 8) * T_ + tcol];
        const float* trow0 = &d_table[dir][ch0][n0];
        const float* trow1 = &d_table[dir][ch1][n0];
#pragma unroll
        for (int jj = 0; jj < 4; jj++) {
            const int colIF = wn * 64 + jj * 16 + 2 * tg;   // (i,f) cols; (g,o) at +8
            const int u_l   = (wn * 4 + jj) * 4 + tg;        // local unit 0..31
#pragma unroll
            for (int half = 0; half < 2; half++) {
                const float* trow = half ? trow1 : trow0;
                const float2 tif = *(const float2*)&trow[colIF];
                const float2 tgo = *(const float2*)&trow[colIF + 8];
                float gi = acc[i][jj * 2 + 0][half * 2 + 0] + tif.x;
                float gf = acc[i][jj * 2 + 0][half * 2 + 1] + tif.y;
                float gg = acc[i][jj * 2 + 1][half * 2 + 0] + tgo.x;
                float go = acc[i][jj * 2 + 1][half * 2 + 1] + tgo.y;
                const int idx = i * 8 + jj * 2 + half;
                float c_new = sig_f(gf) * cv[idx] + sig_f(gi) * tanhf(gg);
                cv[idx] = c_new;
                const float hv = sig_f(go) * tanhf(c_new);
                const __nv_bfloat16 hb = __float2bfloat16(hv);
                const __nv_bfloat16 lb = __float2bfloat16(hv - __bfloat162float(hb));
                const int rl = r0 + half * 8;    // local row 0..127
                // stage into dead smem: hi at OFF_AH(0) area, lo at OFF_BH(0) area
                *(__nv_bfloat16*)(sm + rl * HSTG + u_l * 2) = hb;
                *(__nv_bfloat16*)(sm + 2 * TILE_SZ + rl * HSTG + u_l * 2) = lb;
            }
        }
    }
#pragma unroll
    for (int q = 0; q < 4; q++) *(float4*)&cst[cbase + q * 4] = *(const float4*)&cv[q * 4];

    __syncthreads();
    // coalesced h store: 128 rows x 32 units (64B/row) per split
    const int u0 = n0 >> 2;
#pragma unroll
    for (int it = 0; it < 2; it++) {
        const int idx = tid + it * 256;
        const int row = idx >> 2;
        const int q   = idx & 3;
        uint4 vh = *(const uint4*)(sm + row * HSTG + q * 16);
        uint4 vl = *(const uint4*)(sm + 2 * TILE_SZ + row * HSTG + q * 16);
        *(uint4*)((char*)(hh_n + (size_t)(b0 + row) * H_ + u0) + q * 16) = vh;
        *(uint4*)((char*)(hl_n + (size_t)(b0 + row) * H_ + u0) + q * 16) = vl;
    }
}

// ---------------- classifier head + softmax ----------------
__global__ void head_kernel(const float* __restrict__ Wlin, const float* __restrict__ blin,
                            float* __restrict__ out) {
    const int b    = blockIdx.x;
    const int tid  = threadIdx.x;
    const int w    = tid >> 5;
    const int lane = tid & 31;

    __shared__ __align__(16) float hrow[1024];
    __shared__ float lg[O_];
    __shared__ float red[2];

    for (int i = tid; i < H_; i += 256) {
        hrow[i]      = __bfloat162float(d_hh[0][0][b * H_ + i]) + __bfloat162float(d_hl[0][0][b * H_ + i]);
        hrow[H_ + i] = __bfloat162float(d_hh[1][0][b * H_ + i]) + __bfloat162float(d_hl[1][0][b * H_ + i]);
    }
    __syncthreads();

    const float4* hr4 = (const float4*)hrow;
#pragma unroll
    for (int oo = 0; oo < 8; oo++) {
        const int o = w * 8 + oo;
        const float4* wl = (const float4*)(Wlin + o * 1024);
        float s = 0.f;
#pragma unroll
        for (int it = 0; it < 8; it++) {
            float4 a  = hr4[it * 32 + lane];
            float4 bw = wl[it * 32 + lane];
            s += a.x * bw.x + a.y * bw.y + a.z * bw.z + a.w * bw.w;
        }
#pragma unroll
        for (int off = 16; off; off >>= 1) s += __shfl_down_sync(0xffffffffu, s, off);
        if (lane == 0) lg[o] = s + blin[o];
    }
    __syncthreads();

    if (tid == 0) {
        float m = lg[0];
        for (int i = 1; i < O_; i++) m = fmaxf(m, lg[i]);
        red[0] = m;
    }
    __syncthreads();
    if (tid < O_) lg[tid] = expf(lg[tid] - red[0]);
    __syncthreads();
    if (tid == 0) {
        float s = 0.f;
        for (int i = 0; i < O_; i++) s += lg[i];
        red[1] = 1.0f / s;
    }
    __syncthreads();
    if (tid < O_) out[b * O_ + tid] = lg[tid] * red[1];
}

// ---------------- launch ----------------
extern "C" void kernel_launch(void* const* d_in, const int* in_sizes, int n_in,
                              void* d_out, int out_size) {
    const int*   x    = (const int*)d_in[0];
    const float* emb  = (const float*)d_in[2];
    const float* Wih1 = (const float*)d_in[3];
    const float* Whh1 = (const float*)d_in[4];
    const float* bih1 = (const float*)d_in[5];
    const float* bhh1 = (const float*)d_in[6];
    const float* Wih2 = (const float*)d_in[7];
    const float* Whh2 = (const float*)d_in[8];
    const float* bih2 = (const float*)d_in[9];
    const float* bhh2 = (const float*)d_in[10];
    const float* Wlin = (const float*)d_in[11];
    const float* blin = (const float*)d_in[12];
    float* out = (float*)d_out;

    cudaFuncSetAttribute(lstm_step_mma, cudaFuncAttributeMaxDynamicSharedMemorySize, SMEM_TOTAL);

    dim3 g1(NG / 128, V_, 2);
    build_table<<<g1, 128>>>(emb, Wih1, bih1, bhh1, Wih2, bih2, bhh2);
    dim3 g2(H_ / 128, NG, 2);
    build_wt<<<g2, 128>>>(Whh1, Whh2);
    init_state<<<(B_ * H_ + 255) / 256, 256>>>();

    dim3 gs(NG / 128, B_ / 128, 2);   // (16, 32, 2) = 1024 CTAs, 2/SM
    for (int t = 0; t < T_; t++) {
        lstm_step_mma<<<gs, 256, SMEM_TOTAL>>>(x, t, t & 1);
    }
    head_kernel<<<B_, 256>>>(Wlin, blin, out);
}

// round 7
// speedup vs baseline: 2.4866x; 1.1590x over previous
#include <cuda_runtime.h>
#include <cuda_bf16.h>
#include <math.h>
#include <stdint.h>

#define B_   4096
#define T_   32
#define H_   512
#define NG   2048   // 4*H
#define EMB_ 64
#define V_   256
#define O_   64

// ---------------- persistent scratch ----------------
__device__ float d_table[2][V_][NG];                 // per-char gate preactivation (+biases), mma-column layout
__device__ __nv_bfloat16 d_wh[2][NG][H_];            // Whh hi split, rows = mma columns, K contiguous
__device__ __nv_bfloat16 d_wl[2][NG][H_];            // Whh lo split
__device__ __nv_bfloat16 d_hh[2][2][B_ * H_];        // [dir][pp] h hi split
__device__ __nv_bfloat16 d_hl[2][2][B_ * H_];        // [dir][pp] h lo split
__device__ float d_c[2][B_ * H_];                    // cell state, thread-private coalesced layout

// column n (0..2047) -> torch gate row j
__device__ __forceinline__ int jmap2(int n) {
    int gate = (((n >> 3) & 1) << 1) | (n & 1);
    int u    = ((n >> 4) << 2) | ((n >> 1) & 3);
    return gate * H_ + u;
}
__device__ __forceinline__ float sig_f(float x) {
    return __fdividef(1.0f, 1.0f + __expf(-x));
}
__device__ __forceinline__ float tanh_f(float x) {
    return __fdividef(2.0f, 1.0f + __expf(-2.0f * x)) - 1.0f;
}

// ---------------- PTX helpers (plain-target safe) ----------------
__device__ __forceinline__ uint32_t smem_u32(const void* p) {
    uint32_t a;
    asm("{ .reg .u64 t; cvta.to.shared.u64 t, %1; cvt.u32.u64 %0, t; }" : "=r"(a) : "l"(p));
    return a;
}
__device__ __forceinline__ void cp16(uint32_t saddr, const void* g) {
    asm volatile("cp.async.cg.shared.global [%0], [%1], 16;" :: "r"(saddr), "l"(g));
}
#define CP_COMMIT() asm volatile("cp.async.commit_group;" ::: "memory")
#define CP_WAIT0()  asm volatile("cp.async.wait_group 0;" ::: "memory")
#define CP_WAIT1()  asm volatile("cp.async.wait_group 1;" ::: "memory")

__device__ __forceinline__ void ldsm_x4(uint32_t addr, uint32_t* r) {
    asm volatile("ldmatrix.sync.aligned.m8n8.x4.shared.b16 {%0,%1,%2,%3}, [%4];"
        : "=r"(r[0]), "=r"(r[1]), "=r"(r[2]), "=r"(r[3]) : "r"(addr));
}
__device__ __forceinline__ void mma_bf16(float* c, const uint32_t* a, uint32_t b0, uint32_t b1) {
    asm volatile("mma.sync.aligned.m16n8k16.row.col.f32.bf16.bf16.f32 "
        "{%0,%1,%2,%3}, {%4,%5,%6,%7}, {%8,%9}, {%0,%1,%2,%3};"
        : "+f"(c[0]), "+f"(c[1]), "+f"(c[2]), "+f"(c[3])
        : "r"(a[0]), "r"(a[1]), "r"(a[2]), "r"(a[3]), "r"(b0), "r"(b1));
}

// 64B-row layout, conflict-free swizzle: 16B chunk index ^= (row>>1)&3
__device__ __forceinline__ uint32_t swzoff(int row, int cb) {
    uint32_t chunk = ((uint32_t)cb >> 4) ^ (((uint32_t)row >> 1) & 3u);
    return (uint32_t)row * 64 + chunk * 16;
}

// ---------------- SMEM layout: CTA 128x128, K-tile 32, 3 stages ----------------
#define TILE_SZ  8192
#define STG_SZ   32768
#define NSTG     3
#define OFF_AH(s) ((s) * STG_SZ + 0)
#define OFF_AL(s) ((s) * STG_SZ + TILE_SZ)
#define OFF_BH(s) ((s) * STG_SZ + 2 * TILE_SZ)
#define OFF_BL(s) ((s) * STG_SZ + 3 * TILE_SZ)
#define SMEM_TOTAL (NSTG * STG_SZ)   // 98304
#define HSTG 80                      // h-staging row stride (bytes)

// ---------------- one-off precompute ----------------
__global__ void build_table(const float* __restrict__ emb,
                            const float* __restrict__ Wih1, const float* __restrict__ bih1, const float* __restrict__ bhh1,
                            const float* __restrict__ Wih2, const float* __restrict__ bih2, const float* __restrict__ bhh2) {
    int n   = blockIdx.x * 128 + threadIdx.x;
    int v   = blockIdx.y;
    int dir = blockIdx.z;
    const float* Wih = dir ? Wih2 : Wih1;
    const float* bi  = dir ? bih2 : bih1;
    const float* bh  = dir ? bhh2 : bhh1;
    int j = jmap2(n);
    float s = bi[j] + bh[j];
    const float* e = emb + v * EMB_;
    const float* w = Wih + j * EMB_;
#pragma unroll 16
    for (int k = 0; k < EMB_; k++) s += e[k] * w[k];
    d_table[dir][v][n] = s;
}

__global__ void build_wt(const float* __restrict__ Whh1, const float* __restrict__ Whh2) {
    int k   = blockIdx.x * 128 + threadIdx.x;
    int n   = blockIdx.y;
    int dir = blockIdx.z;
    const float* W = dir ? Whh2 : Whh1;
    float w = W[jmap2(n) * H_ + k];
    __nv_bfloat16 wh = __float2bfloat16(w);
    d_wh[dir][n][k] = wh;
    d_wl[dir][n][k] = __float2bfloat16(w - __bfloat162float(wh));
}

__global__ void init_state() {
    int i = blockIdx.x * 256 + threadIdx.x;
    if (i < B_ * H_) {
        __nv_bfloat16 z = __float2bfloat16(0.f);
        d_hh[0][0][i] = z; d_hh[1][0][i] = z;
        d_hl[0][0][i] = z; d_hl[1][0][i] = z;
        d_c[0][i] = 0.f;   d_c[1][i] = 0.f;
    }
}

// ---------------- async stage: one 128x32 bf16 tile (256 threads) ----------------
__device__ __forceinline__ void stage_tile(uint32_t sdst,
                                           const __nv_bfloat16* __restrict__ src,
                                           int rowbase, int k0, int tid) {
#pragma unroll
    for (int j = 0; j < 2; j++) {
        int lin = tid + j * 256;
        int row = lin >> 2;
        int c   = lin & 3;
        uint32_t chunk = (uint32_t)c ^ (((uint32_t)row >> 1) & 3u);
        cp16(sdst + (uint32_t)row * 64 + chunk * 16,
             (const char*)(src + (size_t)(rowbase + row) * H_ + k0) + c * 16);
    }
}

// ---------------- fused recurrent step on mma.sync tensor cores ----------------
__global__ void __launch_bounds__(256, 2) lstm_step_mma(const int* __restrict__ x, int t, int pp) {
    extern __shared__ __align__(1024) char sm[];
    const int dir  = blockIdx.z;
    const int tcol = dir ? (T_ - 1 - t) : t;
    const int n0   = blockIdx.x * 128;
    const int b0   = blockIdx.y * 128;

    const __nv_bfloat16* __restrict__ hh = d_hh[dir][pp];
    const __nv_bfloat16* __restrict__ hl = d_hl[dir][pp];
    __nv_bfloat16* __restrict__ hh_n = d_hh[dir][pp ^ 1];
    __nv_bfloat16* __restrict__ hl_n = d_hl[dir][pp ^ 1];
    float* __restrict__ cst = d_c[dir];
    const __nv_bfloat16* __restrict__ Wh = &d_wh[dir][0][0];
    const __nv_bfloat16* __restrict__ Wl = &d_wl[dir][0][0];

    const uint32_t sb = smem_u32(sm);
    const int tid  = threadIdx.x;
    const int wid  = tid >> 5;
    const int lane = tid & 31;
    const int wm   = wid >> 1;    // 0..3: 32-row band
    const int wn   = wid & 1;     // 0..1: 64-col band
    const int g    = lane >> 2;
    const int tg   = lane & 3;
    const int lrow  = lane & 15;
    const int lhalf = lane >> 4;

    // prefetch chars for the epilogue (latency off the critical path)
    int chv[2][2];
#pragma unroll
    for (int i = 0; i < 2; i++) {
        const int r0 = wm * 32 + i * 16 + g;
        chv[i][0] = x[(size_t)(b0 + r0) * T_ + tcol];
        chv[i][1] = x[(size_t)(b0 + r0 + 8) * T_ + tcol];
    }

    // per-thread ldsm offsets (loop-invariant)
    uint32_t oA[2][2], oB[4][2];
#pragma unroll
    for (int kk = 0; kk < 2; kk++) {
        const int kb = kk * 32 + lhalf * 16;
#pragma unroll
        for (int i = 0; i < 2; i++) oA[i][kk] = swzoff(wm * 32 + i * 16 + lrow, kb);
#pragma unroll
        for (int q = 0; q < 4; q++) oB[q][kk] = swzoff(wn * 64 + q * 16 + lrow, kb);
    }

    float acc[2][8][4];
#pragma unroll
    for (int i = 0; i < 2; i++)
#pragma unroll
        for (int j = 0; j < 8; j++)
#pragma unroll
            for (int r = 0; r < 4; r++) acc[i][j][r] = 0.f;

    // prologue: stage k-tiles 0 and 1
    stage_tile(sb + OFF_AH(0), hh, b0, 0, tid);
    stage_tile(sb + OFF_AL(0), hl, b0, 0, tid);
    stage_tile(sb + OFF_BH(0), Wh, n0, 0, tid);
    stage_tile(sb + OFF_BL(0), Wl, n0, 0, tid);
    CP_COMMIT();
    stage_tile(sb + OFF_AH(1), hh, b0, 32, tid);
    stage_tile(sb + OFF_AL(1), hl, b0, 32, tid);
    stage_tile(sb + OFF_BH(1), Wh, n0, 32, tid);
    stage_tile(sb + OFF_BL(1), Wl, n0, 32, tid);
    CP_COMMIT();

#pragma unroll
    for (int kt = 0; kt < 16; kt++) {
        if (kt < 15) { CP_WAIT1(); } else { CP_WAIT0(); }
        __syncthreads();
        if (kt + 2 < 16) {
            const int nb = (kt + 2) % NSTG;
            const int k0 = (kt + 2) * 32;
            stage_tile(sb + OFF_AH(nb), hh, b0, k0, tid);
            stage_tile(sb + OFF_AL(nb), hl, b0, k0, tid);
            stage_tile(sb + OFF_BH(nb), Wh, n0, k0, tid);
            stage_tile(sb + OFF_BL(nb), Wl, n0, k0, tid);
            CP_COMMIT();
        }
        const int buf = kt % NSTG;
        const uint32_t baseAH = sb + OFF_AH(buf), baseAL = sb + OFF_AL(buf);
        const uint32_t baseBH = sb + OFF_BH(buf), baseBL = sb + OFF_BL(buf);
#pragma unroll
        for (int kk = 0; kk < 2; kk++) {
            uint32_t af[2][4], bf4[4][4];
            // ---- product 1: lo(A) x hi(B) ----
#pragma unroll
            for (int i = 0; i < 2; i++) ldsm_x4(baseAL + oA[i][kk], af[i]);
#pragma unroll
            for (int q = 0; q < 4; q++) ldsm_x4(baseBH + oB[q][kk], bf4[q]);
#pragma unroll
            for (int i = 0; i < 2; i++)
#pragma unroll
                for (int q = 0; q < 4; q++)
#pragma unroll
                    for (int nb2 = 0; nb2 < 2; nb2++)
                        mma_bf16(acc[i][q * 2 + nb2], af[i], bf4[q][nb2], bf4[q][nb2 + 2]);
            // ---- product 2: hi(A) x hi(B) (reload A only) ----
#pragma unroll
            for (int i = 0; i < 2; i++) ldsm_x4(baseAH + oA[i][kk], af[i]);
#pragma unroll
            for (int i = 0; i < 2; i++)
#pragma unroll
                for (int q = 0; q < 4; q++)
#pragma unroll
                    for (int nb2 = 0; nb2 < 2; nb2++)
                        mma_bf16(acc[i][q * 2 + nb2], af[i], bf4[q][nb2], bf4[q][nb2 + 2]);
            // ---- product 3: hi(A) x lo(B) (reload B only) ----
#pragma unroll
            for (int q = 0; q < 4; q++) ldsm_x4(baseBL + oB[q][kk], bf4[q]);
#pragma unroll
            for (int i = 0; i < 2; i++)
#pragma unroll
                for (int q = 0; q < 4; q++)
#pragma unroll
                    for (int nb2 = 0; nb2 < 2; nb2++)
                        mma_bf16(acc[i][q * 2 + nb2], af[i], bf4[q][nb2], bf4[q][nb2 + 2]);
        }
    }

    __syncthreads();   // all mma smem reads retired before epilogue staging reuse

    // ---------------- epilogue: gates + cell update, in-register ----------------
    const int cbase = (((blockIdx.y * 16 + blockIdx.x) * 256 + tid) << 4);
    float cv[16];
#pragma unroll
    for (int q = 0; q < 4; q++) *(float4*)&cv[q * 4] = *(const float4*)&cst[cbase + q * 4];

#pragma unroll
    for (int i = 0; i < 2; i++) {
        const int r0 = wm * 32 + i * 16 + g;
        const float* trow0 = &d_table[dir][chv[i][0]][n0];
        const float* trow1 = &d_table[dir][chv[i][1]][n0];
#pragma unroll
        for (int jj = 0; jj < 4; jj++) {
            const int colIF = wn * 64 + jj * 16 + 2 * tg;
            const int u_l   = (wn * 4 + jj) * 4 + tg;
#pragma unroll
            for (int half = 0; half < 2; half++) {
                const float* trow = half ? trow1 : trow0;
                const float2 tif = *(const float2*)&trow[colIF];
                const float2 tgo = *(const float2*)&trow[colIF + 8];
                float gi = acc[i][jj * 2 + 0][half * 2 + 0] + tif.x;
                float gf = acc[i][jj * 2 + 0][half * 2 + 1] + tif.y;
                float gg = acc[i][jj * 2 + 1][half * 2 + 0] + tgo.x;
                float go = acc[i][jj * 2 + 1][half * 2 + 1] + tgo.y;
                const int idx = i * 8 + jj * 2 + half;
                float c_new = sig_f(gf) * cv[idx] + sig_f(gi) * tanh_f(gg);
                cv[idx] = c_new;
                const float hv = sig_f(go) * tanh_f(c_new);
                const __nv_bfloat16 hb = __float2bfloat16(hv);
                const __nv_bfloat16 lb = __float2bfloat16(hv - __bfloat162float(hb));
                const int rl = r0 + half * 8;
                *(__nv_bfloat16*)(sm + rl * HSTG + u_l * 2) = hb;
                *(__nv_bfloat16*)(sm + 2 * TILE_SZ + rl * HSTG + u_l * 2) = lb;
            }
        }
    }
#pragma unroll
    for (int q = 0; q < 4; q++) *(float4*)&cst[cbase + q * 4] = *(const float4*)&cv[q * 4];

    __syncthreads();
    const int u0 = n0 >> 2;
#pragma unroll
    for (int it = 0; it < 2; it++) {
        const int idx = tid + it * 256;
        const int row = idx >> 2;
        const int q   = idx & 3;
        uint4 vh = *(const uint4*)(sm + row * HSTG + q * 16);
        uint4 vl = *(const uint4*)(sm + 2 * TILE_SZ + row * HSTG + q * 16);
        *(uint4*)((char*)(hh_n + (size_t)(b0 + row) * H_ + u0) + q * 16) = vh;
        *(uint4*)((char*)(hl_n + (size_t)(b0 + row) * H_ + u0) + q * 16) = vl;
    }
}

// ---------------- classifier head + softmax ----------------
__global__ void head_kernel(const float* __restrict__ Wlin, const float* __restrict__ blin,
                            float* __restrict__ out) {
    const int b    = blockIdx.x;
    const int tid  = threadIdx.x;
    const int w    = tid >> 5;
    const int lane = tid & 31;

    __shared__ __align__(16) float hrow[1024];
    __shared__ float lg[O_];
    __shared__ float red[2];

    for (int i = tid; i < H_; i += 256) {
        hrow[i]      = __bfloat162float(d_hh[0][0][b * H_ + i]) + __bfloat162float(d_hl[0][0][b * H_ + i]);
        hrow[H_ + i] = __bfloat162float(d_hh[1][0][b * H_ + i]) + __bfloat162float(d_hl[1][0][b * H_ + i]);
    }
    __syncthreads();

    const float4* hr4 = (const float4*)hrow;
#pragma unroll
    for (int oo = 0; oo < 8; oo++) {
        const int o = w * 8 + oo;
        const float4* wl = (const float4*)(Wlin + o * 1024);
        float s = 0.f;
#pragma unroll
        for (int it = 0; it < 8; it++) {
            float4 a  = hr4[it * 32 + lane];
            float4 bw = wl[it * 32 + lane];
            s += a.x * bw.x + a.y * bw.y + a.z * bw.z + a.w * bw.w;
        }
#pragma unroll
        for (int off = 16; off; off >>= 1) s += __shfl_down_sync(0xffffffffu, s, off);
        if (lane == 0) lg[o] = s + blin[o];
    }
    __syncthreads();

    if (tid == 0) {
        float m = lg[0];
        for (int i = 1; i < O_; i++) m = fmaxf(m, lg[i]);
        red[0] = m;
    }
    __syncthreads();
    if (tid < O_) lg[tid] = expf(lg[tid] - red[0]);
    __syncthreads();
    if (tid == 0) {
        float s = 0.f;
        for (int i = 0; i < O_; i++) s += lg[i];
        red[1] = 1.0f / s;
    }
    __syncthreads();
    if (tid < O_) out[b * O_ + tid] = lg[tid] * red[1];
}

// ---------------- launch ----------------
extern "C" void kernel_launch(void* const* d_in, const int* in_sizes, int n_in,
                              void* d_out, int out_size) {
    const int*   x    = (const int*)d_in[0];
    const float* emb  = (const float*)d_in[2];
    const float* Wih1 = (const float*)d_in[3];
    const float* Whh1 = (const float*)d_in[4];
    const float* bih1 = (const float*)d_in[5];
    const float* bhh1 = (const float*)d_in[6];
    const float* Wih2 = (const float*)d_in[7];
    const float* Whh2 = (const float*)d_in[8];
    const float* bih2 = (const float*)d_in[9];
    const float* bhh2 = (const float*)d_in[10];
    const float* Wlin = (const float*)d_in[11];
    const float* blin = (const float*)d_in[12];
    float* out = (float*)d_out;

    cudaFuncSetAttribute(lstm_step_mma, cudaFuncAttributeMaxDynamicSharedMemorySize, SMEM_TOTAL);

    dim3 g1(NG / 128, V_, 2);
    build_table<<<g1, 128>>>(emb, Wih1, bih1, bhh1, Wih2, bih2, bhh2);
    dim3 g2(H_ / 128, NG, 2);
    build_wt<<<g2, 128>>>(Whh1, Whh2);
    init_state<<<(B_ * H_ + 255) / 256, 256>>>();

    dim3 gs(NG / 128, B_ / 128, 2);   // (16, 32, 2) = 1024 CTAs, 2/SM
    for (int t = 0; t < T_; t++) {
        lstm_step_mma<<<gs, 256, SMEM_TOTAL>>>(x, t, t & 1);
    }
    head_kernel<<<B_, 256>>>(Wlin, blin, out);
}